// round 15
// baseline (speedup 1.0000x reference)
#include <cuda_runtime.h>
#include <math.h>

#define NB     8
#define D_IN   514
#define T_IN   4000
#define T_OUT  3999
#define NCOL   32                // FFT columns per block
#define NOUT   29                // output columns per block (3 halo)
#define ST     33                // plane row stride (in float2), odd
#define NTHR   512

// Slot permutation left by the in-place DFT16: F[k] lives at slot sigma(k).
#define SIGMA(k) ((((k) & 3) << 2) | ((k) >> 2))

// dynamic smem: A[256*ST] float2 | tw[132] float2 | tw2[256] float2
#define SM_A    0
#define SM_TW   (256 * ST)
#define SM_TW2  (256 * ST + 132)
#define SM_F2   (256 * ST + 132 + 256)
#define SMEM_BYTES (SM_F2 * 8)

// ---------------------------------------------------------------------------
// 16-pt complex DFT, e^{+} kernel, IN PLACE. Output at slot SIGMA(k).
// ---------------------------------------------------------------------------
__device__ __forceinline__ void dft16_ip(float* xr, float* xi) {
    const float W16R[16] = { 1.0f,  0.923879533f,  0.707106781f,  0.382683432f,
                             0.0f, -0.382683432f, -0.707106781f, -0.923879533f,
                            -1.0f, -0.923879533f, -0.707106781f, -0.382683432f,
                             0.0f,  0.382683432f,  0.707106781f,  0.923879533f };
    const float W16I[16] = { 0.0f,  0.382683432f,  0.707106781f,  0.923879533f,
                             1.0f,  0.923879533f,  0.707106781f,  0.382683432f,
                             0.0f, -0.382683432f, -0.707106781f, -0.923879533f,
                            -1.0f, -0.923879533f, -0.707106781f, -0.382683432f };
#pragma unroll
    for (int b = 0; b < 4; b++) {
        float a0r = xr[b],      a0i = xi[b];
        float a1r = xr[b + 4],  a1i = xi[b + 4];
        float a2r = xr[b + 8],  a2i = xi[b + 8];
        float a3r = xr[b + 12], a3i = xi[b + 12];
        float t0r = a0r + a2r, t0i = a0i + a2i;
        float t1r = a0r - a2r, t1i = a0i - a2i;
        float t2r = a1r + a3r, t2i = a1i + a3i;
        float t3r = a1r - a3r, t3i = a1i - a3i;
        float p0r = t0r + t2r, p0i = t0i + t2i;
        float p1r = t1r - t3i, p1i = t1i + t3r;   // + i*t3
        float p2r = t0r - t2r, p2i = t0i - t2i;
        float p3r = t1r + t3i, p3i = t1i - t3r;   // - i*t3
        xr[b] = p0r;  xi[b] = p0i;
#pragma unroll
        for (int jj = 1; jj < 4; jj++) {
            float pr = (jj == 1) ? p1r : (jj == 2) ? p2r : p3r;
            float pi = (jj == 1) ? p1i : (jj == 2) ? p2i : p3i;
            float wr = W16R[(b * jj) & 15], wi = W16I[(b * jj) & 15];
            xr[b + 4 * jj] = pr * wr - pi * wi;
            xi[b + 4 * jj] = pr * wi + pi * wr;
        }
    }
#pragma unroll
    for (int jj = 0; jj < 4; jj++) {
        float b0r = xr[4 * jj],     b0i = xi[4 * jj];
        float b1r = xr[4 * jj + 1], b1i = xi[4 * jj + 1];
        float b2r = xr[4 * jj + 2], b2i = xi[4 * jj + 2];
        float b3r = xr[4 * jj + 3], b3i = xi[4 * jj + 3];
        float t0r = b0r + b2r, t0i = b0i + b2i;
        float t1r = b0r - b2r, t1i = b0i - b2i;
        float t2r = b1r + b3r, t2i = b1i + b3i;
        float t3r = b1r - b3r, t3i = b1i - b3i;
        xr[4 * jj]     = t0r + t2r;  xi[4 * jj]     = t0i + t2i;
        xr[4 * jj + 1] = t1r - t3i;  xi[4 * jj + 1] = t1i + t3r;
        xr[4 * jj + 2] = t0r - t2r;  xi[4 * jj + 2] = t0i - t2i;
        xr[4 * jj + 3] = t1r + t3i;  xi[4 * jj + 3] = t1i - t3r;
    }
}

// ---------------------------------------------------------------------------
// Fused: direct-from-global G build into registers -> 256-pt register FFT
// (16x16 CT, one smem exchange) -> windowed OLA. 512 thr, 32 cols, 29 out.
// ---------------------------------------------------------------------------
__global__ __launch_bounds__(NTHR, 2) void fused_kernel(const float* __restrict__ in,
                                                        const float* __restrict__ win,
                                                        float* __restrict__ out) {
    extern __shared__ float2 sm[];
    float2* A   = sm + SM_A;      // row stride ST (float2)
    float2* tw  = sm + SM_TW;     // e^{+pi i k/256}, k = 0..128
    float2* tw2 = sm + SM_TW2;    // e^{+2pi i m/256}

    const int tid = threadIdx.x;
    const int c   = tid & 31;
    const int lk  = tid >> 5;                 // 0..15, warp-uniform
    const int b   = blockIdx.y;
    const int t0  = blockIdx.x * NOUT;
    const bool interior = (blockIdx.x != 0) && (blockIdx.x != gridDim.x - 1);
    const float* base = in + (size_t)b * D_IN * T_IN + t0 - 3 + c;

    if (tid < 129)
        tw[tid] = make_float2(cospif(tid / 256.0f), sinpif(tid / 256.0f));
    else if (tid >= 256 && tid < 512) {
        int m = tid - 256;
        tw2[m] = make_float2(cospif(m / 128.0f), sinpif(m / 128.0f));
    }
    __syncthreads();

    // Column validity (only matters for edge blocks)
    const int gt = t0 - 3 + c;
    const bool valid = interior || ((gt >= 0) && (gt < T_IN));

    float xr[16], xi[16];

    // ---- Phase 1: G[16a+lk] built directly from global into registers ----
    // a<8: k=16a+lk, kp=k, normal form; a>=8: kp=16(16-a)-lk, partner form.
    // kp=0 (a=0,lk=0) touches rows 256/513 (in-bounds garbage) - fixed below.
#pragma unroll
    for (int a = 0; a < 16; a++) {
        const int kp = (a < 8) ? (16 * a + lk) : (16 * (16 - a) - lk);
        float rk = 0.0f, mk = 0.0f, rp = 0.0f, mp = 0.0f;
        if (valid) {
            rk = base[(size_t)kp * T_IN];
            mk = base[(size_t)(257 + kp) * T_IN];
            rp = base[(size_t)(256 - kp) * T_IN];
            mp = base[(size_t)(513 - kp) * T_IN];
        }
        float Er = rk + rp, Ei = mp - mk;
        float Dr = rk - rp, Di = -(mk + mp);
        float2 w = tw[kp];                    // warp-uniform -> broadcast
        float Or = Dr * w.x - Di * w.y;
        float Oi = Dr * w.y + Di * w.x;
        if (a < 8) { xr[a] = Er - Oi; xi[a] = Ei + Or; }
        else       { xr[a] = Er + Oi; xi[a] = Or - Ei; }
    }
    if (lk == 0) {                            // warp-uniform fix-up: G[0]
        float r0 = valid ? base[0] : 0.0f;
        xr[0] = r0;
        xi[0] = r0;
    }
    dft16_ip(xr, xi);     // F1[k1] at slot SIGMA(k1)

    // ---- Mid twiddle from table: F1[k1] *= W256^{+n2*k1} ----
#pragma unroll
    for (int k1 = 1; k1 < 16; k1++) {
        int s = SIGMA(k1);
        float2 w = tw2[lk * k1];
        float fr = xr[s], fi = xi[s];
        xr[s] = fr * w.x - fi * w.y;
        xi[s] = fr * w.y + fi * w.x;
    }

    // ---- Exchange write: H[n2][k1] at row 16*k1 + n2 (A is dead storage,
    //      no barrier needed before these stores) ----
#pragma unroll
    for (int k1 = 0; k1 < 16; k1++) {
        int s = SIGMA(k1);
        A[(16 * k1 + lk) * ST + c] = make_float2(xr[s], xi[s]);
    }
    __syncthreads();

    // ---- Phase 2: thread (c, k1=lk): Y[n2] = H[n2][k1] ----
#pragma unroll
    for (int n2 = 0; n2 < 16; n2++) {
        float2 v = A[(16 * lk + n2) * ST + c];
        xr[n2] = v.x;
        xi[n2] = v.y;
    }
    dft16_ip(xr, xi);     // F2[k2] at slot SIGMA(k2)
    __syncthreads();      // phase-2 reads done before store-back overwrites

    // ---- Store z[q] at row q = lk + 16*k2 ----
#pragma unroll
    for (int k2 = 0; k2 < 16; k2++) {
        int s = SIGMA(k2);
        A[(lk + 16 * k2) * ST + c] = make_float2(xr[s], xi[s]);
    }
    __syncthreads();

    // ---- Epilogue: out[b,t0+dt,j] = w1*S1[dt+3] + w2*S2[dt+2]
    //                               + w3*S1[dt+1] + w4*S2[dt]
    //      512 thr = 256 j x 2 dt-halves. Rolling 4-tap window. ----
    {
        const int j   = tid & 255;
        const int th  = tid >> 8;
        const int dt0 = th * 15;          // th=0: dt 0..14, th=1: dt 15..28
        const float w1 = 256.0f * __ldg(&win[1023 - j]);
        const float w2 = 256.0f * __ldg(&win[767 - j]);
        const float w3 = 256.0f * __ldg(&win[511 - j]);
        const float w4 = 256.0f * __ldg(&win[255 - j]);

        const float* Af = (const float*)A;
        const int n1 = 511 - j;
        const int f1 = ((n1 >> 1) * ST) * 2 + (n1 & 1);
        const int f2 = (((255 - j) >> 1) * ST) * 2 + (n1 & 1);
        float p1a = Af[f1 + (dt0 + 1) * 2];
        float p1b = Af[f1 + (dt0 + 2) * 2];
        float p2a = Af[f2 + (dt0 + 0) * 2];
        float p2b = Af[f2 + (dt0 + 1) * 2];

        float* ob = out + ((size_t)b * T_OUT + t0) * 256 + j;
        const int nq = th ? (NOUT - 15) : 15;   // 15 / 14
        if (interior) {
#pragma unroll
            for (int q = 0; q < 15; q++) {
                if (q >= nq) break;
                int dt = dt0 + q;
                float n1v = Af[f1 + (dt + 3) * 2];
                float n2v = Af[f2 + (dt + 2) * 2];
                float v = w1 * n1v + w2 * n2v + w3 * p1a + w4 * p2a;
                ob[(size_t)dt * 256] = v;
                p1a = p1b; p1b = n1v;
                p2a = p2b; p2b = n2v;
            }
        } else {
#pragma unroll
            for (int q = 0; q < 15; q++) {
                if (q >= nq) break;
                int dt = dt0 + q;
                if (t0 + dt >= T_OUT) break;
                float n1v = Af[f1 + (dt + 3) * 2];
                float n2v = Af[f2 + (dt + 2) * 2];
                float v = w1 * n1v + w2 * n2v + w3 * p1a + w4 * p2a;
                ob[(size_t)dt * 256] = v;
                p1a = p1b; p1b = n1v;
                p2a = p2b; p2b = n2v;
            }
        }
    }
}

// ---------------------------------------------------------------------------
extern "C" void kernel_launch(void* const* d_in, const int* in_sizes, int n_in,
                              void* d_out, int out_size) {
    const float* in  = (const float*)d_in[0];   // (8, 514, 4000) f32
    const float* win = (const float*)d_in[1];   // (1024,) f32
    float* out = (float*)d_out;                 // (8, 3999*256) f32

    cudaFuncSetAttribute(fused_kernel,
                         cudaFuncAttributeMaxDynamicSharedMemorySize, SMEM_BYTES);

    dim3 g((T_OUT + NOUT - 1) / NOUT, NB);      // (138, 8)
    fused_kernel<<<g, NTHR, SMEM_BYTES>>>(in, win, out);
}

// round 16
// speedup vs baseline: 1.0572x; 1.0572x over previous
#include <cuda_runtime.h>
#include <math.h>

#define NB     8
#define D_IN   514
#define T_IN   4000
#define T_OUT  3999
#define NCOL   32                // FFT columns per block
#define NOUT   29                // output columns per block (3 halo)
#define ST     33                // plane row stride (in float2), odd
#define NTHR   512

// Slot permutation left by the in-place DFT16: F[k] lives at slot sigma(k).
#define SIGMA(k) ((((k) & 3) << 2) | ((k) >> 2))
// Store-back row map: z[q] (q = lk + 16*k2) lives at row 16*lk + ((k2+lk)&15).
// Keeps store-back inside the writer's own phase-2 row set (no barrier) and
// spreads epilogue rows across all banks.
#define ZROW(q) ((((q) & 15) << 4) | ((((q) >> 4) + (q)) & 15))

// dynamic smem: A[256*ST] float2 | tw[128] float2 | tw2[256] float2
#define SM_A    0
#define SM_TW   (256 * ST)
#define SM_TW2  (256 * ST + 128)
#define SM_F2   (256 * ST + 128 + 256)
#define SMEM_BYTES (SM_F2 * 8)

// ---------------------------------------------------------------------------
// 16-pt complex DFT, e^{+} kernel, IN PLACE. Output at slot SIGMA(k).
// ---------------------------------------------------------------------------
__device__ __forceinline__ void dft16_ip(float* xr, float* xi) {
    const float W16R[16] = { 1.0f,  0.923879533f,  0.707106781f,  0.382683432f,
                             0.0f, -0.382683432f, -0.707106781f, -0.923879533f,
                            -1.0f, -0.923879533f, -0.707106781f, -0.382683432f,
                             0.0f,  0.382683432f,  0.707106781f,  0.923879533f };
    const float W16I[16] = { 0.0f,  0.382683432f,  0.707106781f,  0.923879533f,
                             1.0f,  0.923879533f,  0.707106781f,  0.382683432f,
                             0.0f, -0.382683432f, -0.707106781f, -0.923879533f,
                            -1.0f, -0.923879533f, -0.707106781f, -0.382683432f };
#pragma unroll
    for (int b = 0; b < 4; b++) {
        float a0r = xr[b],      a0i = xi[b];
        float a1r = xr[b + 4],  a1i = xi[b + 4];
        float a2r = xr[b + 8],  a2i = xi[b + 8];
        float a3r = xr[b + 12], a3i = xi[b + 12];
        float t0r = a0r + a2r, t0i = a0i + a2i;
        float t1r = a0r - a2r, t1i = a0i - a2i;
        float t2r = a1r + a3r, t2i = a1i + a3i;
        float t3r = a1r - a3r, t3i = a1i - a3i;
        float p0r = t0r + t2r, p0i = t0i + t2i;
        float p1r = t1r - t3i, p1i = t1i + t3r;   // + i*t3
        float p2r = t0r - t2r, p2i = t0i - t2i;
        float p3r = t1r + t3i, p3i = t1i - t3r;   // - i*t3
        xr[b] = p0r;  xi[b] = p0i;
#pragma unroll
        for (int jj = 1; jj < 4; jj++) {
            float pr = (jj == 1) ? p1r : (jj == 2) ? p2r : p3r;
            float pi = (jj == 1) ? p1i : (jj == 2) ? p2i : p3i;
            float wr = W16R[(b * jj) & 15], wi = W16I[(b * jj) & 15];
            xr[b + 4 * jj] = pr * wr - pi * wi;
            xi[b + 4 * jj] = pr * wi + pi * wr;
        }
    }
#pragma unroll
    for (int jj = 0; jj < 4; jj++) {
        float b0r = xr[4 * jj],     b0i = xi[4 * jj];
        float b1r = xr[4 * jj + 1], b1i = xi[4 * jj + 1];
        float b2r = xr[4 * jj + 2], b2i = xi[4 * jj + 2];
        float b3r = xr[4 * jj + 3], b3i = xi[4 * jj + 3];
        float t0r = b0r + b2r, t0i = b0i + b2i;
        float t1r = b0r - b2r, t1i = b0i - b2i;
        float t2r = b1r + b3r, t2i = b1i + b3i;
        float t3r = b1r - b3r, t3i = b1i - b3i;
        xr[4 * jj]     = t0r + t2r;  xi[4 * jj]     = t0i + t2i;
        xr[4 * jj + 1] = t1r - t3i;  xi[4 * jj + 1] = t1i + t3r;
        xr[4 * jj + 2] = t0r - t2r;  xi[4 * jj + 2] = t0i - t2i;
        xr[4 * jj + 3] = t1r + t3i;  xi[4 * jj + 3] = t1i - t3r;
    }
}

// ---------------------------------------------------------------------------
// Fused: conj-sym pack -> 256-pt register FFT (16x16 CT) -> windowed OLA.
// 512 threads, 32 FFT cols (3 halo), 29 outputs per block. 4 barriers.
// ---------------------------------------------------------------------------
__global__ __launch_bounds__(NTHR, 2) void fused_kernel(const float* __restrict__ in,
                                                        const float* __restrict__ win,
                                                        float* __restrict__ out) {
    extern __shared__ float2 sm[];
    float2* A   = sm + SM_A;      // row stride ST (float2)
    float2* tw  = sm + SM_TW;     // e^{+pi i k/256}
    float2* tw2 = sm + SM_TW2;    // e^{+2pi i m/256}

    const int tid = threadIdx.x;
    const int c   = tid & 31;
    const int lk  = tid >> 5;                 // 0..15
    const int b   = blockIdx.y;
    const int t0  = blockIdx.x * NOUT;
    const float* base = in + (size_t)b * D_IN * T_IN + t0 - 3;

    if (tid < 128)
        tw[tid] = make_float2(cospif(tid / 256.0f), sinpif(tid / 256.0f));
    else if (tid < 384) {
        int m = tid - 128;
        tw2[m] = make_float2(cospif(m / 128.0f), sinpif(m / 128.0f));
    }
    __syncthreads();                                       // [1]

    // ---- Build G[k] (zero out-of-range columns) ----
#pragma unroll
    for (int it = 0; it < 9; it++) {
        int idx = tid + it * NTHR;
        if (idx >= 129 * NCOL) break;
        int kp = idx >> 5;
        int cc = idx & 31;
        int gt = t0 - 3 + cc;
        bool v = (gt >= 0) && (gt < T_IN);
        if (kp == 0) {
            float r0 = v ? base[cc] : 0.0f;
            A[cc] = make_float2(r0, r0);
        } else if (kp == 128) {
            float r = v ? base[(size_t)128 * T_IN + cc] : 0.0f;
            float m = v ? base[(size_t)385 * T_IN + cc] : 0.0f;   // 257+128
            A[128 * ST + cc] = make_float2(2.0f * r, 2.0f * m);
        } else {
            float rk = 0.0f, mk = 0.0f, rp = 0.0f, mp = 0.0f;
            if (v) {
                rk = base[(size_t)kp * T_IN + cc];
                mk = base[(size_t)(257 + kp) * T_IN + cc];
                rp = base[(size_t)(256 - kp) * T_IN + cc];
                mp = base[(size_t)(513 - kp) * T_IN + cc];
            }
            float Er = rk + rp, Ei = mp - mk;
            float Dr = rk - rp, Di = -(mk + mp);
            float2 w = tw[kp];
            float Or = Dr * w.x - Di * w.y;
            float Oi = Dr * w.y + Di * w.x;
            A[kp * ST + cc]         = make_float2(Er - Oi, Ei + Or);
            A[(256 - kp) * ST + cc] = make_float2(Er + Oi, Or - Ei);
        }
    }
    __syncthreads();                                       // [2]

    float xr[16], xi[16];

    // ---- Phase 1: thread (c, n2=lk): X[a] = G[16a+lk] (rows ≡ lk mod 16) ----
#pragma unroll
    for (int a = 0; a < 16; a++) {
        float2 v = A[(16 * a + lk) * ST + c];
        xr[a] = v.x;
        xi[a] = v.y;
    }
    dft16_ip(xr, xi);     // F1[k1] at slot SIGMA(k1)

    // ---- Mid twiddle: F1[k1] *= W256^{+lk*k1} ----
#pragma unroll
    for (int k1 = 1; k1 < 16; k1++) {
        int s = SIGMA(k1);
        float2 w = tw2[lk * k1];
        float fr = xr[s], fi = xi[s];
        xr[s] = fr * w.x - fi * w.y;
        xi[s] = fr * w.y + fi * w.x;
    }

    // ---- Exchange: H[n2=lk][k1] at row 16*k1 + lk — same thread-private
    //      row set (≡ lk mod 16, own col) as the phase-1 reads: NO barrier. ----
#pragma unroll
    for (int k1 = 0; k1 < 16; k1++) {
        int s = SIGMA(k1);
        A[(16 * k1 + lk) * ST + c] = make_float2(xr[s], xi[s]);
    }
    __syncthreads();                                       // [3]

    // ---- Phase 2: thread (c, k1=lk): Y[n2] = H[n2][k1] (rows 16lk..16lk+15) ----
#pragma unroll
    for (int n2 = 0; n2 < 16; n2++) {
        float2 v = A[(16 * lk + n2) * ST + c];
        xr[n2] = v.x;
        xi[n2] = v.y;
    }
    dft16_ip(xr, xi);     // F2[k2] at slot SIGMA(k2)

    // ---- Store z[q] (q = lk+16k2) at row ZROW(q) = 16lk + ((k2+lk)&15):
    //      stays inside this thread's phase-2 row set: NO barrier. ----
#pragma unroll
    for (int k2 = 0; k2 < 16; k2++) {
        int s = SIGMA(k2);
        A[(16 * lk + ((k2 + lk) & 15)) * ST + c] = make_float2(xr[s], xi[s]);
    }
    __syncthreads();                                       // [4]

    // ---- Epilogue: out[b,t0+dt,j] = w1*S1[dt+3] + w2*S2[dt+2]
    //                               + w3*S1[dt+1] + w4*S2[dt]
    //      S[n] -> comp (n&1) of row ZROW(n>>1). 256 j x 2 dt-halves. ----
    {
        const int j   = tid & 255;
        const int th  = tid >> 8;
        const int dt0 = th * 15;          // th=0: dt 0..14, th=1: dt 15..28
        const float w1 = 256.0f * __ldg(&win[1023 - j]);
        const float w2 = 256.0f * __ldg(&win[767 - j]);
        const float w3 = 256.0f * __ldg(&win[511 - j]);
        const float w4 = 256.0f * __ldg(&win[255 - j]);

        const float* Af = (const float*)A;
        const int n1 = 511 - j;
        const int q1 = n1 >> 1;
        const int q2 = (255 - j) >> 1;
        const int f1 = ZROW(q1) * ST * 2 + (n1 & 1);
        const int f2 = ZROW(q2) * ST * 2 + (n1 & 1);   // same parity
        float p1a = Af[f1 + (dt0 + 1) * 2];
        float p1b = Af[f1 + (dt0 + 2) * 2];
        float p2a = Af[f2 + (dt0 + 0) * 2];
        float p2b = Af[f2 + (dt0 + 1) * 2];

        float* ob = out + ((size_t)b * T_OUT + t0) * 256 + j;
        const int nq = th ? (NOUT - 15) : 15;   // 15 / 14
#pragma unroll
        for (int q = 0; q < 15; q++) {
            if (q >= nq) break;
            int dt = dt0 + q;
            if (t0 + dt >= T_OUT) break;
            float n1v = Af[f1 + (dt + 3) * 2];
            float n2v = Af[f2 + (dt + 2) * 2];
            float v = w1 * n1v + w2 * n2v + w3 * p1a + w4 * p2a;
            ob[(size_t)dt * 256] = v;
            p1a = p1b; p1b = n1v;
            p2a = p2b; p2b = n2v;
        }
    }
}

// ---------------------------------------------------------------------------
extern "C" void kernel_launch(void* const* d_in, const int* in_sizes, int n_in,
                              void* d_out, int out_size) {
    const float* in  = (const float*)d_in[0];   // (8, 514, 4000) f32
    const float* win = (const float*)d_in[1];   // (1024,) f32
    float* out = (float*)d_out;                 // (8, 3999*256) f32

    cudaFuncSetAttribute(fused_kernel,
                         cudaFuncAttributeMaxDynamicSharedMemorySize, SMEM_BYTES);

    dim3 g((T_OUT + NOUT - 1) / NOUT, NB);      // (138, 8)
    fused_kernel<<<g, NTHR, SMEM_BYTES>>>(in, win, out);
}